// round 17
// baseline (speedup 1.0000x reference)
#include <cuda_runtime.h>
#include <cuda_bf16.h>
#include <cstdint>

// Batched scatter-add: out[b, tgt[b,e], :] += messages[b, e, :]
//   messages (B=32, E=8192, D=128) fp32 | tgt (B=32, E=8192) int32
//   out      (B=32, N=2048, D=128) fp32
//
// R17: R13/R15 structure with ROWS 8 -> 16 via software pipelining.
// Two 4-row batches live at a time (same ~60 reg peak); grid halves and
// index-fetch/loop overhead amortizes 2x.
static constexpr int B = 32;
static constexpr int E = 8192;
static constexpr int N = 2048;
static constexpr int D = 128;               // 32 float4 per row
static constexpr int ROWS = 16;             // rows per warp, 4-row pipeline
static constexpr int WARPS = 8;             // warps per block
static constexpr int OUT_F4 = B * N * D / 4;   // 2097152 float4

// ── Primary: zero the output. PDL trigger at entry; 2x-unrolled STG.128.
__global__ __launch_bounds__(256) void zero_out(float4* __restrict__ out4)
{
    asm volatile("griddepcontrol.launch_dependents;" ::: "memory");
    const float4 z = make_float4(0.f, 0.f, 0.f, 0.f);
    const int stride = gridDim.x * 512;
    int i = blockIdx.x * 512 + threadIdx.x;
    for (; i + 256 < OUT_F4; i += stride) {
        out4[i]       = z;
        out4[i + 256] = z;
    }
    if (i < OUT_F4) out4[i] = z;
}

// Helper: scatter one 4-row batch (rows g*4..g*4+3 of this warp).
__device__ __forceinline__ void scatter4(
    float* __restrict__ out, const float4* v, int row0, int g,
    int t, int t2, int lane)
{
#pragma unroll
    for (int j = 0; j < 4; j++) {
        const int r   = g * 4 + j;                 // row index within warp
        const int src = r >> 1;                    // lane holding this pair
        const int tr  = (r & 1) ? __shfl_sync(0xFFFFFFFFu, t2, src)
                                : __shfl_sync(0xFFFFFFFFu, t,  src);
        const int b   = (row0 + r) >> 13;          // row / E
        float* dst = out + ((size_t)(b * N + tr) * D) + lane * 4;
        asm volatile(
            "red.global.add.v4.f32 [%0], {%1, %2, %3, %4};"
            :: "l"(dst), "f"(v[j].x), "f"(v[j].y), "f"(v[j].z), "f"(v[j].w)
            : "memory");
    }
}

// ── Secondary (PDL): batch 0 loads pre-wait; post-wait pipeline
//    {load batch g+1, scatter batch g} keeps 2 batches live (8 float4).
__global__ __launch_bounds__(WARPS * 32) void scatter_add(
    const float4* __restrict__ messages,   // (B*E, 32) float4
    const int*    __restrict__ tgt,        // (B*E,)
    float*        __restrict__ out)        // (B*N*D,)
{
    const int warp = blockIdx.x * WARPS + (threadIdx.x >> 5);
    const int lane = threadIdx.x & 31;
    const int row0 = warp * ROWS;

    // Index fetch: lanes 0..7 load int2 pairs (covers all 16 rows).
    int t = 0, t2 = 0;
    if (lane < ROWS / 2) {
        const int2 p = __ldg((const int2*)&tgt[row0 + lane * 2]);
        t  = p.x;
        t2 = p.y;
    }

    // Pre-wait: batch 0 (rows 0..3).
    float4 a[4];
#pragma unroll
    for (int j = 0; j < 4; j++)
        a[j] = __ldcs(&messages[(size_t)(row0 + j) * 32 + lane]);

    asm volatile("griddepcontrol.wait;" ::: "memory");

    // Post-wait pipeline over 4 batches: load g+1, scatter g.
    float4 bbuf[4];
#pragma unroll
    for (int g = 0; g < 4; g++) {
        float4* cur  = (g & 1) ? bbuf : a;
        float4* next = (g & 1) ? a : bbuf;
        if (g < 3) {
#pragma unroll
            for (int j = 0; j < 4; j++)
                next[j] = __ldcs(
                    &messages[(size_t)(row0 + (g + 1) * 4 + j) * 32 + lane]);
        }
        scatter4(out, cur, row0, g, t, t2, lane);
    }
}

extern "C" void kernel_launch(void* const* d_in, const int* in_sizes, int n_in,
                              void* d_out, int out_size)
{
    const float4* messages = (const float4*)d_in[0];
    const int*    tgt      = (const int*)d_in[1];

    // Primary: zero kernel.
    zero_out<<<1184, 256>>>((float4*)d_out);

    // Secondary: scatter with programmatic dependent launch.
    cudaLaunchConfig_t cfg = {};
    const int total_rows = B * E;                       // 262144
    cfg.gridDim  = dim3(total_rows / (WARPS * ROWS));   // 2048
    cfg.blockDim = dim3(WARPS * 32);
    cfg.dynamicSmemBytes = 0;
    cfg.stream = 0;
    cudaLaunchAttribute attr[1];
    attr[0].id = cudaLaunchAttributeProgrammaticStreamSerialization;
    attr[0].val.programmaticStreamSerializationAllowed = 1;
    cfg.attrs = attr;
    cfg.numAttrs = 1;
    cudaLaunchKernelEx(&cfg, scatter_add, messages, tgt, (float*)d_out);
}